// round 8
// baseline (speedup 1.0000x reference)
#include <cuda_runtime.h>
#include <mma.h>
#include <cstdint>

using namespace nvcuda;

#define NB     32
#define NC     512
#define NHEADS 8
#define ND     64
#define NSP    4096   // H*W

// Scratch (no allocations allowed)
__device__ float g_W2[(size_t)NB * NC * NC];          // tf32-rounded W @ blockdiag(A)
__device__ float g_Gr[(size_t)NB * NC * NSP];         // tf32-rounded G

// ---------------------------------------------------------------------------
// helpers
// ---------------------------------------------------------------------------
__device__ __forceinline__ uint32_t smem_u32(const void* p) {
    uint32_t a;
    asm("{ .reg .u64 t; cvta.to.shared.u64 t, %1; cvt.u32.u64 %0, t; }" : "=r"(a) : "l"(p));
    return a;
}
__device__ __forceinline__ void cp16(void* dst_smem, const void* src) {
    asm volatile("cp.async.cg.shared.global [%0], [%1], 16;"
                 :: "r"(smem_u32(dst_smem)), "l"(src));
}
#define CP_COMMIT() asm volatile("cp.async.commit_group;" ::: "memory")
#define CP_WAIT(n)  asm volatile("cp.async.wait_group %0;" :: "n"(n) : "memory")

template <class Frag>
__device__ __forceinline__ void round_frag(Frag& f) {
    #pragma unroll
    for (int e = 0; e < f.num_elements; ++e)
        f.x[e] = wmma::__float_to_tf32(f.x[e]);
}

__device__ __forceinline__ void st_tf32_4(float* p, float4 v) {
    float4 o;
    o.x = wmma::__float_to_tf32(v.x);
    o.y = wmma::__float_to_tf32(v.y);
    o.z = wmma::__float_to_tf32(v.z);
    o.w = wmma::__float_to_tf32(v.w);
    *(float4*)p = o;
}

// ---------------------------------------------------------------------------
// Kernel 1: per (b,h).  2-stage cp.async over 64x32 chunks; exact fp32 sumsq
// from raw SMEM; Gram via tf32 WMMA (in-register rounding); writes
// tf32-rounded G chunk to g_Gr along the way.  Softmax, then
// W2 slice = round(W[:,h*64:+64] @ A) stored rounded.
// ---------------------------------------------------------------------------
#define LDA1 36
#define STG1 (2 * 64 * LDA1)   // one stage: L(64x36) + G(64x36)
#define LDS1 68

__global__ __launch_bounds__(256) void attn_kernel(
    const float* __restrict__ localf,
    const float* __restrict__ globalf,
    const float* __restrict__ temp,
    const float* __restrict__ projw)
{
    __shared__ float sMem[2 * STG1];
    __shared__ float sInv[128];
    float* sS = sMem;

    const int h = blockIdx.x;
    const int b = blockIdx.y;
    const float* Lp = localf  + (size_t)(b * NC + h * ND) * NSP;
    const float* Gp = globalf + (size_t)(b * NC + h * ND) * NSP;

    const int t    = threadIdx.x;
    const int lane = t & 31;
    const int warp = t >> 5;
    const int srow = t >> 2;         // 0..63
    const int scol = (t & 3) * 8;    // 0,8,16,24

    const int m0 = (warp & 1) * 32;
    const int n0 = (warp >> 1) * 16;

    wmma::fragment<wmma::accumulator, 16, 16, 8, float> acc0, acc1;
    wmma::fill_fragment(acc0, 0.0f);
    wmma::fill_fragment(acc1, 0.0f);

    float sqL = 0.f, sqG = 0.f;

    const float* lsrc = Lp + (size_t)srow * NSP + scol;
    const float* gsrc = Gp + (size_t)srow * NSP + scol;
    float* ldst  = sMem + srow * LDA1 + scol;
    float* gdst  = sMem + 64 * LDA1 + srow * LDA1 + scol;
    float* grout = g_Gr + ((size_t)(b * NC + h * ND) + srow) * NSP + scol;

    #pragma unroll
    for (int kc = 0; kc < 2; ++kc) {
        float* dl = ldst + kc * STG1;
        float* dg = gdst + kc * STG1;
        cp16(dl, lsrc + kc * 32); cp16(dl + 4, lsrc + kc * 32 + 4);
        cp16(dg, gsrc + kc * 32); cp16(dg + 4, gsrc + kc * 32 + 4);
        CP_COMMIT();
    }

    for (int kc = 0; kc < 128; ++kc) {
        CP_WAIT(1);
        __syncthreads();

        float* stg = sMem + (kc & 1) * STG1;
        float* sL = stg;
        float* sG = stg + 64 * LDA1;

        // exact fp32 sum-of-squares + rounded G write-out
        {
            const float4* lp4 = (const float4*)(sL + srow * LDA1 + scol);
            const float4* gp4 = (const float4*)(sG + srow * LDA1 + scol);
            float4 l0 = lp4[0], l1 = lp4[1], g0 = gp4[0], g1 = gp4[1];
            sqL += l0.x*l0.x + l0.y*l0.y + l0.z*l0.z + l0.w*l0.w
                 + l1.x*l1.x + l1.y*l1.y + l1.z*l1.z + l1.w*l1.w;
            sqG += g0.x*g0.x + g0.y*g0.y + g0.z*g0.z + g0.w*g0.w
                 + g1.x*g1.x + g1.y*g1.y + g1.z*g1.z + g1.w*g1.w;
            st_tf32_4(grout + kc * 32,     g0);
            st_tf32_4(grout + kc * 32 + 4, g1);
        }

        #pragma unroll
        for (int kk = 0; kk < 32; kk += 8) {
            wmma::fragment<wmma::matrix_b, 16, 16, 8, wmma::precision::tf32, wmma::col_major> bf;
            wmma::load_matrix_sync(bf, sG + n0 * LDA1 + kk, LDA1);
            round_frag(bf);
            wmma::fragment<wmma::matrix_a, 16, 16, 8, wmma::precision::tf32, wmma::row_major> af;
            wmma::load_matrix_sync(af, sL + m0 * LDA1 + kk, LDA1);
            round_frag(af);
            wmma::mma_sync(acc0, af, bf, acc0);
            wmma::load_matrix_sync(af, sL + (m0 + 16) * LDA1 + kk, LDA1);
            round_frag(af);
            wmma::mma_sync(acc1, af, bf, acc1);
        }
        __syncthreads();

        if (kc + 2 < 128) {
            const int kn = kc + 2;
            float* dl = ldst + (kn & 1) * STG1;
            float* dg = gdst + (kn & 1) * STG1;
            cp16(dl, lsrc + kn * 32); cp16(dl + 4, lsrc + kn * 32 + 4);
            cp16(dg, gsrc + kn * 32); cp16(dg + 4, gsrc + kn * 32 + 4);
            CP_COMMIT();
        } else {
            CP_COMMIT();
        }
    }

    sqL += __shfl_xor_sync(0xffffffffu, sqL, 1);
    sqL += __shfl_xor_sync(0xffffffffu, sqL, 2);
    sqG += __shfl_xor_sync(0xffffffffu, sqG, 1);
    sqG += __shfl_xor_sync(0xffffffffu, sqG, 2);
    if ((t & 3) == 0) {
        sInv[srow]      = 1.f / fmaxf(sqrtf(sqL), 1e-12f);
        sInv[64 + srow] = 1.f / fmaxf(sqrtf(sqG), 1e-12f);
    }

    wmma::store_matrix_sync(sS + m0 * LDS1 + n0, acc0, LDS1, wmma::mem_row_major);
    wmma::store_matrix_sync(sS + (m0 + 16) * LDS1 + n0, acc1, LDS1, wmma::mem_row_major);
    __syncthreads();

    const float tval = temp[h];
    for (int rr = warp * 8; rr < warp * 8 + 8; ++rr) {
        float il = sInv[rr] * tval;
        float x1 = sS[rr * LDS1 + lane]      * il * sInv[64 + lane];
        float x2 = sS[rr * LDS1 + 32 + lane] * il * sInv[96 + lane];
        float mx = fmaxf(x1, x2);
        #pragma unroll
        for (int o = 16; o > 0; o >>= 1)
            mx = fmaxf(mx, __shfl_xor_sync(0xffffffffu, mx, o));
        float e1 = expf(x1 - mx);
        float e2 = expf(x2 - mx);
        float s = e1 + e2;
        #pragma unroll
        for (int o = 16; o > 0; o >>= 1)
            s += __shfl_xor_sync(0xffffffffu, s, o);
        float is = 1.f / s;
        sS[rr * LDS1 + lane]      = wmma::__float_to_tf32(e1 * is);
        sS[rr * LDS1 + 32 + lane] = wmma::__float_to_tf32(e2 * is);
    }
    __syncthreads();

    // W2 slice: [512 x 64] = W[:, h*64:+64] @ A ; stored tf32-rounded
    const int o0 = warp * 64;
    wmma::fragment<wmma::accumulator, 16, 16, 8, float> wacc[4][4];
    #pragma unroll
    for (int i = 0; i < 4; ++i)
        #pragma unroll
        for (int j = 0; j < 4; ++j)
            wmma::fill_fragment(wacc[i][j], 0.0f);

    #pragma unroll
    for (int kk = 0; kk < 64; kk += 8) {
        wmma::fragment<wmma::matrix_b, 16, 16, 8, wmma::precision::tf32, wmma::row_major> bf[4];
        #pragma unroll
        for (int j = 0; j < 4; ++j)
            wmma::load_matrix_sync(bf[j], sS + kk * LDS1 + j * 16, LDS1);
        #pragma unroll
        for (int i = 0; i < 4; ++i) {
            wmma::fragment<wmma::matrix_a, 16, 16, 8, wmma::precision::tf32, wmma::row_major> af;
            wmma::load_matrix_sync(af, projw + (size_t)(o0 + i * 16) * NC + h * ND + kk, NC);
            round_frag(af);
            #pragma unroll
            for (int j = 0; j < 4; ++j)
                wmma::mma_sync(wacc[i][j], af, bf[j], wacc[i][j]);
        }
    }
    float* w2p = g_W2 + (size_t)b * NC * NC;
    #pragma unroll
    for (int i = 0; i < 4; ++i)
        #pragma unroll
        for (int j = 0; j < 4; ++j) {
            round_frag(wacc[i][j]);   // pre-round A operand of proj GEMM
            wmma::store_matrix_sync(w2p + (size_t)(o0 + i * 16) * NC + h * ND + j * 16,
                                    wacc[i][j], NC, wmma::mem_row_major);
        }
}

// ---------------------------------------------------------------------------
// Kernel 2: out[b] = W2[b] (512x512) @ Gr[b] (512x4096), tf32 WMMA.
// CTA tile 128(m) x 256(n), 512 threads / 16 warps (2m x 8n), warp tile 64x32.
// KT=32, 3-stage cp.async pipeline.  NO in-loop rounding (operands pre-rounded).
// ---------------------------------------------------------------------------
#define KTP  32
#define LDAP 36
#define LDBP 260
#define ASZP (128 * LDAP)        // 4608 floats
#define BSZP (KTP * LDBP)        // 8320 floats
#define STGP (ASZP + BSZP)       // 12928 floats
#define NSTG 3

__global__ __launch_bounds__(512) void proj_kernel(float* __restrict__ outp)
{
    extern __shared__ float psm[];   // NSTG * STGP floats

    const int b  = blockIdx.z;
    const int o0 = blockIdx.y * 128;
    const int n0 = blockIdx.x * 256;
    const float* Ap = g_W2 + (size_t)b * NC * NC + (size_t)o0 * NC;   // [128][512]
    const float* Bp = g_Gr + (size_t)b * NC * NSP + n0;               // [512][256 window]

    const int t    = threadIdx.x;
    const int warp = t >> 5;
    const int mw = (warp & 1) * 64;     // 0 or 64
    const int nw = (warp >> 1) * 32;    // 0..224

    // cp.async mappings (512 threads)
    const int ar = t >> 2,  aq = (t & 3) * 8;    // A: 128r x 32k, 8 floats/thr
    const int br = t >> 4,  bq = (t & 15) * 16;  // B: 32r x 256n, 16 floats/thr

    wmma::fragment<wmma::accumulator, 16, 16, 8, float> acc[4][2];
    #pragma unroll
    for (int i = 0; i < 4; ++i)
        #pragma unroll
        for (int j = 0; j < 2; ++j)
            wmma::fill_fragment(acc[i][j], 0.0f);

    const float* agBase = Ap + (size_t)ar * NC + aq;
    const float* bgBase = Bp + (size_t)br * NSP + bq;

    #pragma unroll
    for (int kc = 0; kc < NSTG; ++kc) {
        float* sa = psm + kc * STGP;
        float* sb = sa + ASZP;
        const float* ag = agBase + kc * KTP;
        const float* bg = bgBase + (size_t)kc * KTP * NSP;
        cp16(sa + ar * LDAP + aq,     ag);
        cp16(sa + ar * LDAP + aq + 4, ag + 4);
        #pragma unroll
        for (int j = 0; j < 4; ++j)
            cp16(sb + br * LDBP + bq + j * 4, bg + j * 4);
        CP_COMMIT();
    }

    for (int kc = 0; kc < NC / KTP; ++kc) {
        CP_WAIT(2);
        __syncthreads();

        float* sa = psm + (kc % NSTG) * STGP;
        float* sb = sa + ASZP;

        #pragma unroll
        for (int kk = 0; kk < KTP; kk += 8) {
            wmma::fragment<wmma::matrix_b, 16, 16, 8, wmma::precision::tf32, wmma::row_major> bf[2];
            #pragma unroll
            for (int j = 0; j < 2; ++j)
                wmma::load_matrix_sync(bf[j], sb + kk * LDBP + nw + j * 16, LDBP);
            #pragma unroll
            for (int i = 0; i < 4; ++i) {
                wmma::fragment<wmma::matrix_a, 16, 16, 8, wmma::precision::tf32, wmma::row_major> af;
                wmma::load_matrix_sync(af, sa + (mw + i * 16) * LDAP + kk, LDAP);
                #pragma unroll
                for (int j = 0; j < 2; ++j)
                    wmma::mma_sync(acc[i][j], af, bf[j], acc[i][j]);
            }
        }
        __syncthreads();

        const int kn = kc + NSTG;
        if (kn < NC / KTP) {
            float* na = psm + (kn % NSTG) * STGP;
            float* nb = na + ASZP;
            const float* ag = agBase + kn * KTP;
            const float* bg = bgBase + (size_t)kn * KTP * NSP;
            cp16(na + ar * LDAP + aq,     ag);
            cp16(na + ar * LDAP + aq + 4, ag + 4);
            #pragma unroll
            for (int j = 0; j < 4; ++j)
                cp16(nb + br * LDBP + bq + j * 4, bg + j * 4);
        }
        CP_COMMIT();
    }

    #pragma unroll
    for (int i = 0; i < 4; ++i)
        #pragma unroll
        for (int j = 0; j < 2; ++j)
            wmma::store_matrix_sync(
                outp + (size_t)(b * NC + o0 + mw + i * 16) * NSP + n0 + nw + j * 16,
                acc[i][j], NSP, wmma::mem_row_major);
}

extern "C" void kernel_launch(void* const* d_in, const int* in_sizes, int n_in,
                              void* d_out, int out_size) {
    (void)in_sizes; (void)n_in; (void)out_size;
    const float* localf  = (const float*)d_in[0];
    const float* globalf = (const float*)d_in[1];
    const float* temp    = (const float*)d_in[2];
    const float* projw   = (const float*)d_in[3];
    float* outp = (float*)d_out;

    dim3 g1(NHEADS, NB);
    attn_kernel<<<g1, 256>>>(localf, globalf, temp, projw);

    static_assert(NSTG * STGP * sizeof(float) <= 160 * 1024, "smem budget");
    cudaFuncSetAttribute(proj_kernel, cudaFuncAttributeMaxDynamicSharedMemorySize,
                         NSTG * STGP * (int)sizeof(float));
    dim3 g3(NSP / 256, NC / 128, NB);
    proj_kernel<<<g3, 512, NSTG * STGP * sizeof(float)>>>(outp);
}

// round 9
// speedup vs baseline: 2.7342x; 2.7342x over previous
#include <cuda_runtime.h>
#include <cuda_fp16.h>
#include <mma.h>
#include <cstdint>

using namespace nvcuda;

#define NB     32
#define NC     512
#define NHEADS 8
#define ND     64
#define NSP    4096   // H*W

// Scratch (no allocations allowed)
__device__ __half g_W2[(size_t)NB * NC * NC];     // fp16 W @ blockdiag(A)
__device__ __half g_Gr[(size_t)NB * NC * NSP];    // fp16-rounded G

// ---------------------------------------------------------------------------
// helpers
// ---------------------------------------------------------------------------
__device__ __forceinline__ uint32_t smem_u32(const void* p) {
    uint32_t a;
    asm("{ .reg .u64 t; cvta.to.shared.u64 t, %1; cvt.u32.u64 %0, t; }" : "=r"(a) : "l"(p));
    return a;
}
__device__ __forceinline__ void cp16(void* dst_smem, const void* src) {
    asm volatile("cp.async.cg.shared.global [%0], [%1], 16;"
                 :: "r"(smem_u32(dst_smem)), "l"(src));
}
#define CP_COMMIT() asm volatile("cp.async.commit_group;" ::: "memory")
#define CP_WAIT(n)  asm volatile("cp.async.wait_group %0;" :: "n"(n) : "memory")

__device__ __forceinline__ void st_h8(__half* p, float4 a, float4 b) {
    union { __half2 h[4]; uint4 u; } pk;
    pk.h[0] = __floats2half2_rn(a.x, a.y);
    pk.h[1] = __floats2half2_rn(a.z, a.w);
    pk.h[2] = __floats2half2_rn(b.x, b.y);
    pk.h[3] = __floats2half2_rn(b.z, b.w);
    *(uint4*)p = pk.u;
}

// ---------------------------------------------------------------------------
// Kernel 1: per (b,h).  Phase A: 2-stage cp.async raw staging; exact fp32
// sumsq; convert chunk to fp16 tiles (+ packed fp16 g_Gr write-out); fp16
// WMMA Gram.  Phase B: fp32 softmax -> fp16 A matrix.  Phase C: fp16 WMMA
// W2 slice = W[:,h*64:+64] @ A, W staged per-16k panel as fp16; result
// written fp16 to g_W2.
// ---------------------------------------------------------------------------
#define LDA1 36
#define STG1 (2 * 64 * LDA1)     // raw stage: L(64x36)+G(64x36) floats
#define LDH1 40                  // fp16 tile ld
#define LDS1 68                  // fp32 S tile ld
#define LDSH 72                  // fp16 A tile ld

__global__ __launch_bounds__(256) void attn_kernel(
    const float* __restrict__ localf,
    const float* __restrict__ globalf,
    const float* __restrict__ temp,
    const float* __restrict__ projw)
{
    __shared__ float  sRaw[2 * STG1];          // 36864 B
    __shared__ __half sHalf[2 * 64 * LDH1];    // 10240 B
    __shared__ float  sInv[128];

    float*  sS  = sRaw;                        // 64x68 fp32 (4352 floats)
    __half* sLh = sHalf;
    __half* sGh = sHalf + 64 * LDH1;
    __half* sSh = sHalf;                       // 64x72 fp16 A (4608 halfs)
    __half* sWp = (__half*)(sRaw + 5120);      // 512x16 fp16 W panel (16384 B)

    const int h = blockIdx.x;
    const int b = blockIdx.y;
    const float* Lp = localf  + (size_t)(b * NC + h * ND) * NSP;
    const float* Gp = globalf + (size_t)(b * NC + h * ND) * NSP;

    const int t    = threadIdx.x;
    const int lane = t & 31;
    const int warp = t >> 5;
    const int srow = t >> 2;         // 0..63
    const int scol = (t & 3) * 8;    // 0,8,16,24

    const int m0 = (warp & 1) * 32;
    const int n0 = (warp >> 1) * 16;

    wmma::fragment<wmma::accumulator, 16, 16, 16, float> acc0, acc1;
    wmma::fill_fragment(acc0, 0.0f);
    wmma::fill_fragment(acc1, 0.0f);

    float sqL = 0.f, sqG = 0.f;

    const float* lsrc = Lp + (size_t)srow * NSP + scol;
    const float* gsrc = Gp + (size_t)srow * NSP + scol;
    float*  ldst  = sRaw + srow * LDA1 + scol;
    float*  gdst  = sRaw + 64 * LDA1 + srow * LDA1 + scol;
    __half* grout = g_Gr + ((size_t)(b * NC + h * ND) + srow) * NSP + scol;

    #pragma unroll
    for (int kc = 0; kc < 2; ++kc) {
        float* dl = ldst + kc * STG1;
        float* dg = gdst + kc * STG1;
        cp16(dl, lsrc + kc * 32); cp16(dl + 4, lsrc + kc * 32 + 4);
        cp16(dg, gsrc + kc * 32); cp16(dg + 4, gsrc + kc * 32 + 4);
        CP_COMMIT();
    }

    for (int kc = 0; kc < 128; ++kc) {
        CP_WAIT(1);
        __syncthreads();                       // raw ready + prev MMAs done

        float* stg = sRaw + (kc & 1) * STG1;
        const float4* lp4 = (const float4*)(stg + srow * LDA1 + scol);
        const float4* gp4 = (const float4*)(stg + 64 * LDA1 + srow * LDA1 + scol);
        float4 l0 = lp4[0], l1 = lp4[1], g0 = gp4[0], g1 = gp4[1];

        sqL += l0.x*l0.x + l0.y*l0.y + l0.z*l0.z + l0.w*l0.w
             + l1.x*l1.x + l1.y*l1.y + l1.z*l1.z + l1.w*l1.w;
        sqG += g0.x*g0.x + g0.y*g0.y + g0.z*g0.z + g0.w*g0.w
             + g1.x*g1.x + g1.y*g1.y + g1.z*g1.z + g1.w*g1.w;

        st_h8(sLh + srow * LDH1 + scol, l0, l1);
        st_h8(sGh + srow * LDH1 + scol, g0, g1);
        st_h8(grout + kc * 32, g0, g1);        // fp16-rounded G for proj
        __syncthreads();                       // fp16 tiles complete

        if (kc + 2 < 128) {                    // raw slot now free
            const int kn = kc + 2;
            float* dl = ldst + (kn & 1) * STG1;
            float* dg = gdst + (kn & 1) * STG1;
            cp16(dl, lsrc + kn * 32); cp16(dl + 4, lsrc + kn * 32 + 4);
            cp16(dg, gsrc + kn * 32); cp16(dg + 4, gsrc + kn * 32 + 4);
        }
        CP_COMMIT();

        #pragma unroll
        for (int kk = 0; kk < 32; kk += 16) {
            wmma::fragment<wmma::matrix_b, 16, 16, 16, __half, wmma::col_major> bf;
            wmma::load_matrix_sync(bf, sGh + n0 * LDH1 + kk, LDH1);
            wmma::fragment<wmma::matrix_a, 16, 16, 16, __half, wmma::row_major> af;
            wmma::load_matrix_sync(af, sLh + m0 * LDH1 + kk, LDH1);
            wmma::mma_sync(acc0, af, bf, acc0);
            wmma::load_matrix_sync(af, sLh + (m0 + 16) * LDH1 + kk, LDH1);
            wmma::mma_sync(acc1, af, bf, acc1);
        }
    }
    __syncthreads();

    sqL += __shfl_xor_sync(0xffffffffu, sqL, 1);
    sqL += __shfl_xor_sync(0xffffffffu, sqL, 2);
    sqG += __shfl_xor_sync(0xffffffffu, sqG, 1);
    sqG += __shfl_xor_sync(0xffffffffu, sqG, 2);
    if ((t & 3) == 0) {
        sInv[srow]      = 1.f / fmaxf(sqrtf(sqL), 1e-12f);
        sInv[64 + srow] = 1.f / fmaxf(sqrtf(sqG), 1e-12f);
    }

    wmma::store_matrix_sync(sS + m0 * LDS1 + n0, acc0, LDS1, wmma::mem_row_major);
    wmma::store_matrix_sync(sS + (m0 + 16) * LDS1 + n0, acc1, LDS1, wmma::mem_row_major);
    __syncthreads();

    const float tval = temp[h];
    for (int rr = warp * 8; rr < warp * 8 + 8; ++rr) {
        float il = sInv[rr] * tval;
        float x1 = sS[rr * LDS1 + lane]      * il * sInv[64 + lane];
        float x2 = sS[rr * LDS1 + 32 + lane] * il * sInv[96 + lane];
        float mx = fmaxf(x1, x2);
        #pragma unroll
        for (int o = 16; o > 0; o >>= 1)
            mx = fmaxf(mx, __shfl_xor_sync(0xffffffffu, mx, o));
        float e1 = expf(x1 - mx);
        float e2 = expf(x2 - mx);
        float s = e1 + e2;
        #pragma unroll
        for (int o = 16; o > 0; o >>= 1)
            s += __shfl_xor_sync(0xffffffffu, s, o);
        float is = 1.f / s;
        sSh[rr * LDSH + lane]      = __float2half_rn(e1 * is);
        sSh[rr * LDSH + 32 + lane] = __float2half_rn(e2 * is);
    }
    __syncthreads();

    // Phase C: W2 slice [512 x 64] = W[:, h*64:+64] @ A, fp16 MMA, K panels of 16
    const int o0w = warp * 64;
    const int hk  = h * ND;
    wmma::fragment<wmma::accumulator, 16, 16, 16, float> wacc[4][4];
    #pragma unroll
    for (int i = 0; i < 4; ++i)
        #pragma unroll
        for (int j = 0; j < 4; ++j)
            wmma::fill_fragment(wacc[i][j], 0.0f);

    for (int kg = 0; kg < 4; ++kg) {
        // stage W[512][kg*16..+16] as fp16
        for (int idx = t; idx < 512 * 4; idx += 256) {
            const int o = idx >> 2, q = (idx & 3) * 4;
            float4 wv = *(const float4*)(projw + (size_t)o * NC + hk + kg * 16 + q);
            __half* d = sWp + o * 16 + q;
            d[0] = __float2half_rn(wv.x); d[1] = __float2half_rn(wv.y);
            d[2] = __float2half_rn(wv.z); d[3] = __float2half_rn(wv.w);
        }
        __syncthreads();

        wmma::fragment<wmma::matrix_b, 16, 16, 16, __half, wmma::row_major> bf[4];
        #pragma unroll
        for (int j = 0; j < 4; ++j)
            wmma::load_matrix_sync(bf[j], sSh + (kg * 16) * LDSH + j * 16, LDSH);
        #pragma unroll
        for (int i = 0; i < 4; ++i) {
            wmma::fragment<wmma::matrix_a, 16, 16, 16, __half, wmma::row_major> af;
            wmma::load_matrix_sync(af, sWp + (o0w + i * 16) * 16, 16);
            #pragma unroll
            for (int j = 0; j < 4; ++j)
                wmma::mma_sync(wacc[i][j], af, bf[j], wacc[i][j]);
        }
        __syncthreads();
    }

    // write W2 slice as fp16 via per-warp fp32 scratch
    float* sW = sRaw + warp * 1088;     // 16x68 fp32 slab per warp
    __half* w2p = g_W2 + (size_t)b * NC * NC;
    const int r  = lane >> 1;
    const int c0 = (lane & 1) * 32;
    #pragma unroll
    for (int i = 0; i < 4; ++i) {
        #pragma unroll
        for (int j = 0; j < 4; ++j)
            wmma::store_matrix_sync(sW + j * 16, wacc[i][j], 68, wmma::mem_row_major);
        __syncwarp();
        __half* dst = w2p + (size_t)(o0w + i * 16 + r) * NC + hk + c0;
        #pragma unroll
        for (int q = 0; q < 4; ++q) {
            const float* s = sW + r * 68 + c0 + q * 8;
            float4 a = make_float4(s[0], s[1], s[2], s[3]);
            float4 bq = make_float4(s[4], s[5], s[6], s[7]);
            st_h8(dst + q * 8, a, bq);
        }
        __syncwarp();
    }
}

// ---------------------------------------------------------------------------
// Kernel 2: out[b] = W2[b] (512x512) @ Gr[b] (512x4096), fp16 WMMA.
// CTA tile 128(m) x 256(n), 512 threads / 16 warps (2m x 8n), warp tile 64x32.
// KT=32, 4-stage cp.async pipeline, fp16 operands, fp32 accum.
// ---------------------------------------------------------------------------
#define KTP   32
#define LDAPh 40                  // 128 x 32 fp16 A tile ld
#define LDBPh 264                 // 32 x 256 fp16 B tile ld
#define ASZh  (128 * LDAPh)       // 5120 halfs
#define BSZh  (KTP * LDBPh)       // 8448 halfs
#define STGh  (ASZh + BSZh)       // 13568 halfs = 27136 B
#define NSTG  4

__global__ __launch_bounds__(512) void proj_kernel(float* __restrict__ outp)
{
    extern __shared__ __half psm[];   // NSTG * STGh halfs

    const int b  = blockIdx.z;
    const int o0 = blockIdx.y * 128;
    const int n0 = blockIdx.x * 256;
    const __half* Ap = g_W2 + (size_t)b * NC * NC + (size_t)o0 * NC;
    const __half* Bp = g_Gr + (size_t)b * NC * NSP + n0;

    const int t    = threadIdx.x;
    const int warp = t >> 5;
    const int mw = (warp & 1) * 64;
    const int nw = (warp >> 1) * 32;

    // cp.async mappings (512 threads)
    const int ar = t >> 2,  aq = (t & 3) * 8;    // A: 128r x 32k halfs, 8/thr
    const int br = t >> 4,  bq = (t & 15) * 16;  // B: 32r x 256n halfs, 16/thr

    wmma::fragment<wmma::accumulator, 16, 16, 16, float> acc[4][2];
    #pragma unroll
    for (int i = 0; i < 4; ++i)
        #pragma unroll
        for (int j = 0; j < 2; ++j)
            wmma::fill_fragment(acc[i][j], 0.0f);

    const __half* agBase = Ap + (size_t)ar * NC + aq;
    const __half* bgBase = Bp + (size_t)br * NSP + bq;

    #pragma unroll
    for (int kc = 0; kc < NSTG; ++kc) {
        __half* sa = psm + kc * STGh;
        __half* sb = sa + ASZh;
        cp16(sa + ar * LDAPh + aq, agBase + kc * KTP);
        cp16(sb + br * LDBPh + bq,     bgBase + (size_t)kc * KTP * NSP);
        cp16(sb + br * LDBPh + bq + 8, bgBase + (size_t)kc * KTP * NSP + 8);
        CP_COMMIT();
    }

    for (int kc = 0; kc < NC / KTP; ++kc) {
        CP_WAIT(2);
        __syncthreads();

        __half* sa = psm + (kc % NSTG) * STGh;
        __half* sb = sa + ASZh;

        #pragma unroll
        for (int kk = 0; kk < KTP; kk += 16) {
            wmma::fragment<wmma::matrix_b, 16, 16, 16, __half, wmma::row_major> bf[2];
            #pragma unroll
            for (int j = 0; j < 2; ++j)
                wmma::load_matrix_sync(bf[j], sb + kk * LDBPh + nw + j * 16, LDBPh);
            #pragma unroll
            for (int i = 0; i < 4; ++i) {
                wmma::fragment<wmma::matrix_a, 16, 16, 16, __half, wmma::row_major> af;
                wmma::load_matrix_sync(af, sa + (mw + i * 16) * LDAPh + kk, LDAPh);
                #pragma unroll
                for (int j = 0; j < 2; ++j)
                    wmma::mma_sync(acc[i][j], af, bf[j], acc[i][j]);
            }
        }
        __syncthreads();

        const int kn = kc + NSTG;
        if (kn < NC / KTP) {
            __half* na = psm + (kn % NSTG) * STGh;
            __half* nb = na + ASZh;
            cp16(na + ar * LDAPh + aq, agBase + kn * KTP);
            cp16(nb + br * LDBPh + bq,     bgBase + (size_t)kn * KTP * NSP);
            cp16(nb + br * LDBPh + bq + 8, bgBase + (size_t)kn * KTP * NSP + 8);
        }
        CP_COMMIT();
    }

    #pragma unroll
    for (int i = 0; i < 4; ++i)
        #pragma unroll
        for (int j = 0; j < 2; ++j)
            wmma::store_matrix_sync(
                outp + (size_t)(b * NC + o0 + mw + i * 16) * NSP + n0 + nw + j * 16,
                acc[i][j], NSP, wmma::mem_row_major);
}

extern "C" void kernel_launch(void* const* d_in, const int* in_sizes, int n_in,
                              void* d_out, int out_size) {
    (void)in_sizes; (void)n_in; (void)out_size;
    const float* localf  = (const float*)d_in[0];
    const float* globalf = (const float*)d_in[1];
    const float* temp    = (const float*)d_in[2];
    const float* projw   = (const float*)d_in[3];
    float* outp = (float*)d_out;

    dim3 g1(NHEADS, NB);
    attn_kernel<<<g1, 256>>>(localf, globalf, temp, projw);

    cudaFuncSetAttribute(proj_kernel, cudaFuncAttributeMaxDynamicSharedMemorySize,
                         NSTG * STGh * (int)sizeof(__half));
    dim3 g3(NSP / 256, NC / 128, NB);
    proj_kernel<<<g3, 512, NSTG * STGh * sizeof(__half)>>>(outp);
}

// round 12
// speedup vs baseline: 2.9713x; 1.0867x over previous
#include <cuda_runtime.h>
#include <cuda_fp16.h>
#include <mma.h>
#include <cstdint>

using namespace nvcuda;

#define NB     32
#define NC     512
#define NHEADS 8
#define ND     64
#define NSP    4096   // H*W

// Scratch (no allocations allowed)
__device__ __half g_W2[(size_t)NB * NC * NC];     // fp16 W @ blockdiag(A)
__device__ __half g_Gr[(size_t)NB * NC * NSP];    // fp16-rounded G

// ---------------------------------------------------------------------------
// helpers
// ---------------------------------------------------------------------------
__device__ __forceinline__ uint32_t smem_u32(const void* p) {
    uint32_t a;
    asm("{ .reg .u64 t; cvta.to.shared.u64 t, %1; cvt.u32.u64 %0, t; }" : "=r"(a) : "l"(p));
    return a;
}
__device__ __forceinline__ void cp16(void* dst_smem, const void* src) {
    asm volatile("cp.async.cg.shared.global [%0], [%1], 16;"
                 :: "r"(smem_u32(dst_smem)), "l"(src));
}
#define CP_COMMIT() asm volatile("cp.async.commit_group;" ::: "memory")
#define CP_WAIT(n)  asm volatile("cp.async.wait_group %0;" :: "n"(n) : "memory")

__device__ __forceinline__ void st_h8(__half* p, float4 a, float4 b) {
    union { __half2 h[4]; uint4 u; } pk;
    pk.h[0] = __floats2half2_rn(a.x, a.y);
    pk.h[1] = __floats2half2_rn(a.z, a.w);
    pk.h[2] = __floats2half2_rn(b.x, b.y);
    pk.h[3] = __floats2half2_rn(b.z, b.w);
    *(uint4*)p = pk.u;
}

// ---------------------------------------------------------------------------
// Kernel 1: per (b,h).  Phase A: 4-stage cp.async raw ring (prefetch dist 3);
// exact fp32 sumsq; convert chunk to fp16 tiles (+ fp16 g_Gr write-out);
// fp16 WMMA Gram.  Phase B: fp32 softmax -> fp16 A.  Phase C: fp16 WMMA
// W2 slice = W[:,h*64:+64] @ A -> fp16 g_W2.
// NOTE on safety of issue-before-wait here: iteration kc issues into slot
// (kc+3)&3 == (kc-1)&3.  All raw reads of that slot happened in iter kc-1
// BETWEEN its two __syncthreads; every thread passed the second barrier of
// iter kc-1 before any thread enters iter kc, so no read can be live.
// ---------------------------------------------------------------------------
#define LDA1 36
#define RSTG (64 * LDA1 * 2)     // 4608 floats per raw stage
#define LDH1 40
#define LDS1 68
#define LDSH 72
#define ATTN_DSM (4 * RSTG * 4 + 2 * 64 * LDH1 * 2 * 2 + 512)

__global__ __launch_bounds__(256) void attn_kernel(
    const float* __restrict__ localf,
    const float* __restrict__ globalf,
    const float* __restrict__ temp,
    const float* __restrict__ projw)
{
    extern __shared__ char dsm[];
    float*  sRaw  = (float*)dsm;                         // 4 x 4608 floats
    __half* sHalf = (__half*)(dsm + 4 * RSTG * 4);       // 2 x 5120 halfs
    float*  sInv  = (float*)(dsm + 4 * RSTG * 4 + 2 * 64 * LDH1 * 2 * 2);

    float*  sS  = sRaw;                    // 64x68 fp32 S tile (phase B)
    __half* sSh = sHalf;                   // 64x72 fp16 A tile (phase B/C)
    __half* sWp = (__half*)(sRaw + 5120);  // 512x16 fp16 W panel (phase C)

    const int h = blockIdx.x;
    const int b = blockIdx.y;
    const float* Lp = localf  + (size_t)(b * NC + h * ND) * NSP;
    const float* Gp = globalf + (size_t)(b * NC + h * ND) * NSP;

    const int t    = threadIdx.x;
    const int lane = t & 31;
    const int warp = t >> 5;
    const int srow = t >> 2;         // 0..63
    const int scol = (t & 3) * 8;    // 0,8,16,24

    const int m0 = (warp & 1) * 32;
    const int n0 = (warp >> 1) * 16;

    wmma::fragment<wmma::accumulator, 16, 16, 16, float> acc0, acc1;
    wmma::fill_fragment(acc0, 0.0f);
    wmma::fill_fragment(acc1, 0.0f);

    float sqL = 0.f, sqG = 0.f;

    const float* lsrc = Lp + (size_t)srow * NSP + scol;
    const float* gsrc = Gp + (size_t)srow * NSP + scol;
    const int rawOff = srow * LDA1 + scol;
    __half* grout = g_Gr + ((size_t)(b * NC + h * ND) + srow) * NSP + scol;

    // prologue: chunks 0,1,2
    #pragma unroll
    for (int kc = 0; kc < 3; ++kc) {
        float* dl = sRaw + kc * RSTG + rawOff;
        float* dg = dl + 64 * LDA1;
        cp16(dl, lsrc + kc * 32); cp16(dl + 4, lsrc + kc * 32 + 4);
        cp16(dg, gsrc + kc * 32); cp16(dg + 4, gsrc + kc * 32 + 4);
        CP_COMMIT();
    }

    for (int kc = 0; kc < 128; ++kc) {
        const int kn = kc + 3;
        if (kn < 128) {
            float* dl = sRaw + (kn & 3) * RSTG + rawOff;
            float* dg = dl + 64 * LDA1;
            cp16(dl, lsrc + kn * 32); cp16(dl + 4, lsrc + kn * 32 + 4);
            cp16(dg, gsrc + kn * 32); cp16(dg + 4, gsrc + kn * 32 + 4);
        }
        CP_COMMIT();
        CP_WAIT(3);
        __syncthreads();                       // chunk kc visible to all

        float* stg = sRaw + (kc & 3) * RSTG;
        const float4* lp4 = (const float4*)(stg + rawOff);
        const float4* gp4 = (const float4*)(stg + 64 * LDA1 + rawOff);
        float4 l0 = lp4[0], l1 = lp4[1], g0 = gp4[0], g1 = gp4[1];

        sqL += l0.x*l0.x + l0.y*l0.y + l0.z*l0.z + l0.w*l0.w
             + l1.x*l1.x + l1.y*l1.y + l1.z*l1.z + l1.w*l1.w;
        sqG += g0.x*g0.x + g0.y*g0.y + g0.z*g0.z + g0.w*g0.w
             + g1.x*g1.x + g1.y*g1.y + g1.z*g1.z + g1.w*g1.w;

        __half* sLh = sHalf + (kc & 1) * 5120;
        __half* sGh = sLh + 64 * LDH1;
        st_h8(sLh + srow * LDH1 + scol, l0, l1);
        st_h8(sGh + srow * LDH1 + scol, g0, g1);
        st_h8(grout + kc * 32, g0, g1);        // fp16-rounded G for proj
        __syncthreads();                       // fp16 tiles complete

        #pragma unroll
        for (int kk = 0; kk < 32; kk += 16) {
            wmma::fragment<wmma::matrix_b, 16, 16, 16, __half, wmma::col_major> bf;
            wmma::load_matrix_sync(bf, sGh + n0 * LDH1 + kk, LDH1);
            wmma::fragment<wmma::matrix_a, 16, 16, 16, __half, wmma::row_major> af;
            wmma::load_matrix_sync(af, sLh + m0 * LDH1 + kk, LDH1);
            wmma::mma_sync(acc0, af, bf, acc0);
            wmma::load_matrix_sync(af, sLh + (m0 + 16) * LDH1 + kk, LDH1);
            wmma::mma_sync(acc1, af, bf, acc1);
        }
    }
    __syncthreads();

    sqL += __shfl_xor_sync(0xffffffffu, sqL, 1);
    sqL += __shfl_xor_sync(0xffffffffu, sqL, 2);
    sqG += __shfl_xor_sync(0xffffffffu, sqG, 1);
    sqG += __shfl_xor_sync(0xffffffffu, sqG, 2);
    if ((t & 3) == 0) {
        sInv[srow]      = 1.f / fmaxf(sqrtf(sqL), 1e-12f);
        sInv[64 + srow] = 1.f / fmaxf(sqrtf(sqG), 1e-12f);
    }

    wmma::store_matrix_sync(sS + m0 * LDS1 + n0, acc0, LDS1, wmma::mem_row_major);
    wmma::store_matrix_sync(sS + (m0 + 16) * LDS1 + n0, acc1, LDS1, wmma::mem_row_major);
    __syncthreads();

    const float tval = temp[h];
    for (int rr = warp * 8; rr < warp * 8 + 8; ++rr) {
        float il = sInv[rr] * tval;
        float x1 = sS[rr * LDS1 + lane]      * il * sInv[64 + lane];
        float x2 = sS[rr * LDS1 + 32 + lane] * il * sInv[96 + lane];
        float mx = fmaxf(x1, x2);
        #pragma unroll
        for (int o = 16; o > 0; o >>= 1)
            mx = fmaxf(mx, __shfl_xor_sync(0xffffffffu, mx, o));
        float e1 = expf(x1 - mx);
        float e2 = expf(x2 - mx);
        float s = e1 + e2;
        #pragma unroll
        for (int o = 16; o > 0; o >>= 1)
            s += __shfl_xor_sync(0xffffffffu, s, o);
        float is = 1.f / s;
        sSh[rr * LDSH + lane]      = __float2half_rn(e1 * is);
        sSh[rr * LDSH + 32 + lane] = __float2half_rn(e2 * is);
    }
    __syncthreads();

    // Phase C: W2 slice [512 x 64] = W[:, h*64:+64] @ A, fp16 MMA, K panels of 16
    const int o0w = warp * 64;
    const int hk  = h * ND;
    wmma::fragment<wmma::accumulator, 16, 16, 16, float> wacc[4][4];
    #pragma unroll
    for (int i = 0; i < 4; ++i)
        #pragma unroll
        for (int j = 0; j < 4; ++j)
            wmma::fill_fragment(wacc[i][j], 0.0f);

    for (int kg = 0; kg < 4; ++kg) {
        for (int idx = t; idx < 512 * 4; idx += 256) {
            const int o = idx >> 2, q = (idx & 3) * 4;
            float4 wv = *(const float4*)(projw + (size_t)o * NC + hk + kg * 16 + q);
            __half* d = sWp + o * 16 + q;
            d[0] = __float2half_rn(wv.x); d[1] = __float2half_rn(wv.y);
            d[2] = __float2half_rn(wv.z); d[3] = __float2half_rn(wv.w);
        }
        __syncthreads();

        wmma::fragment<wmma::matrix_b, 16, 16, 16, __half, wmma::row_major> bf[4];
        #pragma unroll
        for (int j = 0; j < 4; ++j)
            wmma::load_matrix_sync(bf[j], sSh + (kg * 16) * LDSH + j * 16, LDSH);
        #pragma unroll
        for (int i = 0; i < 4; ++i) {
            wmma::fragment<wmma::matrix_a, 16, 16, 16, __half, wmma::row_major> af;
            wmma::load_matrix_sync(af, sWp + (o0w + i * 16) * 16, 16);
            #pragma unroll
            for (int j = 0; j < 4; ++j)
                wmma::mma_sync(wacc[i][j], af, bf[j], wacc[i][j]);
        }
        __syncthreads();
    }

    // write W2 slice as fp16 via per-warp fp32 scratch
    float* sW = sRaw + warp * 1088;     // 16x68 fp32 slab per warp
    __half* w2p = g_W2 + (size_t)b * NC * NC;
    const int r  = lane >> 1;
    const int c0 = (lane & 1) * 32;
    #pragma unroll
    for (int i = 0; i < 4; ++i) {
        #pragma unroll
        for (int j = 0; j < 4; ++j)
            wmma::store_matrix_sync(sW + j * 16, wacc[i][j], 68, wmma::mem_row_major);
        __syncwarp();
        __half* dst = w2p + (size_t)(o0w + i * 16 + r) * NC + hk + c0;
        #pragma unroll
        for (int q = 0; q < 4; ++q) {
            const float* s = sW + r * 68 + c0 + q * 8;
            float4 a = make_float4(s[0], s[1], s[2], s[3]);
            float4 bq = make_float4(s[4], s[5], s[6], s[7]);
            st_h8(dst + q * 8, a, bq);
        }
        __syncwarp();
    }
}

// ---------------------------------------------------------------------------
// Kernel 2: out[b] = W2[b] (512x512) @ Gr[b] (512x4096), fp16 WMMA.
// CTA 128(m) x 256(n), 512 thr / 16 warps, warp tile 64x32, KT=32.
// 4-slot cp.async ring, prefetch distance 3, ONE sync per chunk, with the
// prefetch issued AFTER the barrier: the barrier at the top of iter kc is
// passed only once every thread finished iter kc-1's MMA reads of slot
// (kc-1)&3 == (kc+3)&3, making the subsequent write to that slot safe.
// ---------------------------------------------------------------------------
#define KTP   32
#define LDAPh 40
#define LDBPh 264
#define ASZh  (128 * LDAPh)
#define BSZh  (KTP * LDBPh)
#define STGh  (ASZh + BSZh)
#define NSTG  4

__global__ __launch_bounds__(512) void proj_kernel(float* __restrict__ outp)
{
    extern __shared__ __half psm[];

    const int b  = blockIdx.z;
    const int o0 = blockIdx.y * 128;
    const int n0 = blockIdx.x * 256;
    const __half* Ap = g_W2 + (size_t)b * NC * NC + (size_t)o0 * NC;
    const __half* Bp = g_Gr + (size_t)b * NC * NSP + n0;

    const int t    = threadIdx.x;
    const int warp = t >> 5;
    const int mw = (warp & 1) * 64;
    const int nw = (warp >> 1) * 32;

    const int ar = t >> 2,  aq = (t & 3) * 8;
    const int br = t >> 4,  bq = (t & 15) * 16;

    wmma::fragment<wmma::accumulator, 16, 16, 16, float> acc[4][2];
    #pragma unroll
    for (int i = 0; i < 4; ++i)
        #pragma unroll
        for (int j = 0; j < 2; ++j)
            wmma::fill_fragment(acc[i][j], 0.0f);

    const __half* agBase = Ap + (size_t)ar * NC + aq;
    const __half* bgBase = Bp + (size_t)br * NSP + bq;

    // prologue: chunks 0,1,2
    #pragma unroll
    for (int kc = 0; kc < 3; ++kc) {
        __half* sa = psm + kc * STGh;
        __half* sb = sa + ASZh;
        cp16(sa + ar * LDAPh + aq, agBase + kc * KTP);
        cp16(sb + br * LDBPh + bq,     bgBase + (size_t)kc * KTP * NSP);
        cp16(sb + br * LDBPh + bq + 8, bgBase + (size_t)kc * KTP * NSP + 8);
        CP_COMMIT();
    }

    for (int kc = 0; kc < NC / KTP; ++kc) {
        CP_WAIT(2);            // 3 groups pending -> chunk kc complete
        __syncthreads();       // chunk kc visible; slot (kc+3)&3 reads all done

        const int kn = kc + 3;
        if (kn < NC / KTP) {
            __half* na = psm + (kn & 3) * STGh;
            __half* nb = na + ASZh;
            cp16(na + ar * LDAPh + aq, agBase + kn * KTP);
            cp16(nb + br * LDBPh + bq,     bgBase + (size_t)kn * KTP * NSP);
            cp16(nb + br * LDBPh + bq + 8, bgBase + (size_t)kn * KTP * NSP + 8);
        }
        CP_COMMIT();

        __half* sa = psm + (kc & 3) * STGh;
        __half* sb = sa + ASZh;

        #pragma unroll
        for (int kk = 0; kk < KTP; kk += 16) {
            wmma::fragment<wmma::matrix_b, 16, 16, 16, __half, wmma::row_major> bf[2];
            #pragma unroll
            for (int j = 0; j < 2; ++j)
                wmma::load_matrix_sync(bf[j], sb + kk * LDBPh + nw + j * 16, LDBPh);
            #pragma unroll
            for (int i = 0; i < 4; ++i) {
                wmma::fragment<wmma::matrix_a, 16, 16, 16, __half, wmma::row_major> af;
                wmma::load_matrix_sync(af, sa + (mw + i * 16) * LDAPh + kk, LDAPh);
                #pragma unroll
                for (int j = 0; j < 2; ++j)
                    wmma::mma_sync(acc[i][j], af, bf[j], acc[i][j]);
            }
        }
    }

    #pragma unroll
    for (int i = 0; i < 4; ++i)
        #pragma unroll
        for (int j = 0; j < 2; ++j)
            wmma::store_matrix_sync(
                outp + (size_t)(b * NC + o0 + mw + i * 16) * NSP + n0 + nw + j * 16,
                acc[i][j], NSP, wmma::mem_row_major);
}

extern "C" void kernel_launch(void* const* d_in, const int* in_sizes, int n_in,
                              void* d_out, int out_size) {
    (void)in_sizes; (void)n_in; (void)out_size;
    const float* localf  = (const float*)d_in[0];
    const float* globalf = (const float*)d_in[1];
    const float* temp    = (const float*)d_in[2];
    const float* projw   = (const float*)d_in[3];
    float* outp = (float*)d_out;

    cudaFuncSetAttribute(attn_kernel, cudaFuncAttributeMaxDynamicSharedMemorySize,
                         ATTN_DSM);
    dim3 g1(NHEADS, NB);
    attn_kernel<<<g1, 256, ATTN_DSM>>>(localf, globalf, temp, projw);

    cudaFuncSetAttribute(proj_kernel, cudaFuncAttributeMaxDynamicSharedMemorySize,
                         NSTG * STGh * (int)sizeof(__half));
    dim3 g3(NSP / 256, NC / 128, NB);
    proj_kernel<<<g3, 512, NSTG * STGh * sizeof(__half)>>>(outp);
}